// round 5
// baseline (speedup 1.0000x reference)
#include <cuda_runtime.h>
#include <cstdint>

// Quaternion normalization: x viewed as (B, 256, 4); each 4-vector divided by
// its L2 norm (norm==0 -> divide by 1, i.e. pass through zeros).
// Total: 65536 * 1024 floats = 16,777,216 quaternions = 512 MiB R+W traffic.
// HBM-bound; sustained ceiling observed at ~6.55 TB/s for the 1:1 R/W mix.
// R5 experiment: default (.wb) stores so L2 batches writebacks into larger
// DRAM bursts; loads stay .cs (streaming, no L2 pollution from reads).

__device__ __forceinline__ float4 ldg_cs_f4(const float4* p) {
    float4 v;
    asm volatile("ld.global.cs.v4.f32 {%0,%1,%2,%3}, [%4];"
                 : "=f"(v.x), "=f"(v.y), "=f"(v.z), "=f"(v.w)
                 : "l"(p));
    return v;
}

__device__ __forceinline__ void stg_wb_f4(float4* p, float4 v) {
    asm volatile("st.global.wb.v4.f32 [%0], {%1,%2,%3,%4};"
                 :: "l"(p), "f"(v.x), "f"(v.y), "f"(v.z), "f"(v.w));
}

__device__ __forceinline__ float4 norm_quat(float4 q) {
    float s = q.x * q.x + q.y * q.y + q.z * q.z + q.w * q.w;
    float inv = (s == 0.0f) ? 1.0f : rsqrtf(s);
    q.x *= inv; q.y *= inv; q.z *= inv; q.w *= inv;
    return q;
}

// Bulk kernel: branch-free, 8 quaternions per thread, interleaved within the
// block (index = block_base + tid + k*blockDim) so every LDG.128/STG.128 is
// fully coalesced (lane stride 16B). Loads front-batched for MLP=8.
__global__ void __launch_bounds__(256) quat_norm_bulk(
    const float4* __restrict__ in, float4* __restrict__ out)
{
    const int T = 256;
    int64_t base = (int64_t)blockIdx.x * (T * 8) + threadIdx.x;

    float4 q[8];
#pragma unroll
    for (int k = 0; k < 8; k++)
        q[k] = ldg_cs_f4(in + base + (int64_t)k * T);
#pragma unroll
    for (int k = 0; k < 8; k++)
        q[k] = norm_quat(q[k]);
#pragma unroll
    for (int k = 0; k < 8; k++)
        stg_wb_f4(out + base + (int64_t)k * T, q[k]);
}

// Tail kernel: one quaternion per thread with bounds check (empty here).
__global__ void __launch_bounds__(256) quat_norm_tail(
    const float4* __restrict__ in, float4* __restrict__ out,
    int64_t start, int64_t n_quats)
{
    int64_t i = start + (int64_t)blockIdx.x * blockDim.x + threadIdx.x;
    if (i < n_quats) {
        float4 a = ldg_cs_f4(in + i);
        stg_wb_f4(out + i, norm_quat(a));
    }
}

extern "C" void kernel_launch(void* const* d_in, const int* in_sizes, int n_in,
                              void* d_out, int out_size) {
    const float4* in = (const float4*)d_in[0];
    float4* out = (float4*)d_out;
    int64_t n_quats = (int64_t)in_sizes[0] / 4;   // 16,777,216

    const int threads = 256;
    const int64_t quats_per_block = (int64_t)threads * 8;   // 2048
    int64_t bulk_blocks = n_quats / quats_per_block;        // 8192 (exact)

    if (bulk_blocks > 0)
        quat_norm_bulk<<<(unsigned)bulk_blocks, threads>>>(in, out);

    int64_t done = bulk_blocks * quats_per_block;
    int64_t rem = n_quats - done;
    if (rem > 0) {
        int tail_blocks = (int)((rem + threads - 1) / threads);
        quat_norm_tail<<<tail_blocks, threads>>>(in, out, done, n_quats);
    }
}

// round 6
// speedup vs baseline: 1.0066x; 1.0066x over previous
#include <cuda_runtime.h>
#include <cstdint>

// Quaternion normalization: x viewed as (B, 256, 4); each 4-vector divided by
// its L2 norm (norm==0 -> divide by 1, i.e. pass through zeros).
// Total: 65536 * 1024 floats = 16,777,216 quaternions = 512 MiB R+W traffic.
//
// FINAL: HBM-bound at the 1:1 R/W streaming ceiling (~6.5 TB/s sustained).
// Established across R2-R5: unroll depth (2/4/8), store policy (.cs/.wb),
// occupancy (60-79%) are all neutral; coalescing (lane stride 16B per
// LDG.128) is the only thing that mattered (R3: blocked layout regressed 6%).
// Config: 4 quats/thread, block-interleaved indexing, .cs loads+stores.

__device__ __forceinline__ float4 ldg_cs_f4(const float4* p) {
    float4 v;
    asm volatile("ld.global.cs.v4.f32 {%0,%1,%2,%3}, [%4];"
                 : "=f"(v.x), "=f"(v.y), "=f"(v.z), "=f"(v.w)
                 : "l"(p));
    return v;
}

__device__ __forceinline__ void stg_cs_f4(float4* p, float4 v) {
    asm volatile("st.global.cs.v4.f32 [%0], {%1,%2,%3,%4};"
                 :: "l"(p), "f"(v.x), "f"(v.y), "f"(v.z), "f"(v.w));
}

__device__ __forceinline__ float4 norm_quat(float4 q) {
    float s = q.x * q.x + q.y * q.y + q.z * q.z + q.w * q.w;
    float inv = (s == 0.0f) ? 1.0f : rsqrtf(s);
    q.x *= inv; q.y *= inv; q.z *= inv; q.w *= inv;
    return q;
}

// Bulk kernel: branch-free, 4 quaternions per thread, interleaved within the
// block (index = block_base + tid + k*blockDim) so every LDG.128/STG.128 is
// fully coalesced (lane stride 16B -> 4 contiguous 128B lines per wavefront).
// Loads front-batched for MLP=4.
__global__ void __launch_bounds__(256) quat_norm_bulk(
    const float4* __restrict__ in, float4* __restrict__ out)
{
    const int T = 256;
    int64_t base = (int64_t)blockIdx.x * (T * 4) + threadIdx.x;
    float4 a = ldg_cs_f4(in + base + 0 * T);
    float4 b = ldg_cs_f4(in + base + 1 * T);
    float4 c = ldg_cs_f4(in + base + 2 * T);
    float4 d = ldg_cs_f4(in + base + 3 * T);
    a = norm_quat(a);
    b = norm_quat(b);
    c = norm_quat(c);
    d = norm_quat(d);
    stg_cs_f4(out + base + 0 * T, a);
    stg_cs_f4(out + base + 1 * T, b);
    stg_cs_f4(out + base + 2 * T, c);
    stg_cs_f4(out + base + 3 * T, d);
}

// Tail kernel: one quaternion per thread with bounds check (empty for this
// problem's shape; kept for generality).
__global__ void __launch_bounds__(256) quat_norm_tail(
    const float4* __restrict__ in, float4* __restrict__ out,
    int64_t start, int64_t n_quats)
{
    int64_t i = start + (int64_t)blockIdx.x * blockDim.x + threadIdx.x;
    if (i < n_quats) {
        float4 a = ldg_cs_f4(in + i);
        stg_cs_f4(out + i, norm_quat(a));
    }
}

extern "C" void kernel_launch(void* const* d_in, const int* in_sizes, int n_in,
                              void* d_out, int out_size) {
    const float4* in = (const float4*)d_in[0];
    float4* out = (float4*)d_out;
    int64_t n_quats = (int64_t)in_sizes[0] / 4;   // 16,777,216

    const int threads = 256;
    const int64_t quats_per_block = (int64_t)threads * 4;   // 1024
    int64_t bulk_blocks = n_quats / quats_per_block;        // 16384 (exact)

    if (bulk_blocks > 0)
        quat_norm_bulk<<<(unsigned)bulk_blocks, threads>>>(in, out);

    int64_t done = bulk_blocks * quats_per_block;
    int64_t rem = n_quats - done;
    if (rem > 0) {
        int tail_blocks = (int)((rem + threads - 1) / threads);
        quat_norm_tail<<<tail_blocks, threads>>>(in, out, done, n_quats);
    }
}